// round 4
// baseline (speedup 1.0000x reference)
#include <cuda_runtime.h>

// CostVolume1D: out[n,d,h,w] = (1/C) * sum_c f1[n,c,h,w] * f2pad[n,c,h,w+d-4]
// f1,f2: [4,128,192,640] fp32. Barrier-free streaming kernel, float2 per thread
// (2x thread count vs float4 version -> more resident warps -> more MLP).

#define Nn   4
#define Cc   128
#define Hh   192
#define Ww   640
#define Dd   4
#define NS   (2*Dd + 1)          // 9
#define TPB  128
#define VW2  (Ww / 2)            // 320 float2 per row
#define CH2  ((size_t)Hh * VW2)  // channel stride in float2 units (61440)

__global__ __launch_bounds__(TPB)
void costvol1d_kernel(const float2* __restrict__ f1,
                      const float2* __restrict__ f2,
                      float2* __restrict__ out)
{
    const int gid = blockIdx.x * TPB + threadIdx.x;   // 0 .. N*H*VW2-1 = 245759
    const int v   = gid % VW2;         // float2 index within row
    const int row = gid / VW2;         // n*Hh + h
    const int n   = row / Hh;
    const int h   = row % Hh;

    // window = f2pad floats [2v-4 .. 2v+5] -> float2 indices v-2 .. v+2
    const bool p0 = (v >= 2);
    const bool p1 = (v >= 1);
    const bool p3 = (v <= VW2 - 2);
    const bool p4 = (v <= VW2 - 3);

    const size_t base = ((size_t)n * Cc * Hh + h) * VW2 + v;   // channel 0

    float acc[NS * 2];
    #pragma unroll
    for (int i = 0; i < NS * 2; i++) acc[i] = 0.0f;

    const float2 z2 = make_float2(0.f, 0.f);

    #pragma unroll 4
    for (int c = 0; c < Cc; c++) {
        const size_t o = base + (size_t)c * CH2;

        const float2 a  = f1[o];
        const float2 m2 = p0 ? f2[o - 2] : z2;
        const float2 m1 = p1 ? f2[o - 1] : z2;
        const float2 c0 = f2[o];
        const float2 q1 = p3 ? f2[o + 1] : z2;
        const float2 q2 = p4 ? f2[o + 2] : z2;

        // wf[k] = f2pad[2v-4+k], k = 0..9
        float wf[10];
        wf[0] = m2.x; wf[1] = m2.y;
        wf[2] = m1.x; wf[3] = m1.y;
        wf[4] = c0.x; wf[5] = c0.y;
        wf[6] = q1.x; wf[7] = q1.y;
        wf[8] = q2.x; wf[9] = q2.y;

        // output (2v+j, shift d) uses f2pad[2v+j+d-4] = wf[j+d]
        #pragma unroll
        for (int d = 0; d < NS; d++) {
            acc[d * 2 + 0] = fmaf(a.x, wf[d],     acc[d * 2 + 0]);
            acc[d * 2 + 1] = fmaf(a.y, wf[d + 1], acc[d * 2 + 1]);
        }
    }

    // Epilogue: channel mean, float2 stores. out[n][d][h][2v..2v+1]
    const float inv = 1.0f / (float)Cc;
    #pragma unroll
    for (int d = 0; d < NS; d++) {
        float2 o2;
        o2.x = acc[d * 2 + 0] * inv;
        o2.y = acc[d * 2 + 1] * inv;
        out[((size_t)(n * NS + d) * Hh + h) * VW2 + v] = o2;
    }
}

extern "C" void kernel_launch(void* const* d_in, const int* in_sizes, int n_in,
                              void* d_out, int out_size)
{
    const float2* f1 = (const float2*)d_in[0];
    const float2* f2 = (const float2*)d_in[1];
    float2* out = (float2*)d_out;
    (void)in_sizes; (void)n_in; (void)out_size;

    const int total = Nn * Hh * VW2;          // 245760 threads, 1 float2 each
    dim3 grid(total / TPB);                   // 1920 blocks
    dim3 block(TPB);
    costvol1d_kernel<<<grid, block>>>(f1, f2, out);
}

// round 5
// speedup vs baseline: 1.1023x; 1.1023x over previous
#include <cuda_runtime.h>

// CostVolume1D: out[n,d,h,w] = (1/C) * sum_c f1[n,c,h,w] * f2pad[n,c,h,w+d-4]
// f1,f2: [4,128,192,640] fp32. Barrier-free, smem-free, float4 per thread.
// R5: TPB=64 (grid 1920 -> 12.97 CTAs/SM, even wave balance),
//     streaming cache hints (__ldcs on read-once f1, __stcs on stores).

#define Nn   4
#define Cc   128
#define Hh   192
#define Ww   640
#define Dd   4
#define NS   (2*Dd + 1)       // 9
#define TPB  64
#define VW   (Ww / 4)         // 160 float4 per row
#define CH4  ((size_t)Hh * VW) // channel stride in float4 units (30720)

__global__ __launch_bounds__(TPB)
void costvol1d_kernel(const float4* __restrict__ f1,
                      const float4* __restrict__ f2,
                      float* __restrict__ out)
{
    const int gid = blockIdx.x * TPB + threadIdx.x;   // 0 .. N*H*VW-1 = 122879
    const int v   = gid % VW;          // float4 index within row
    const int row = gid / VW;          // n*Hh + h
    const int n   = row / Hh;
    const int h   = row % Hh;

    const bool pm = (v > 0);           // left-edge window valid?
    const bool pp = (v < VW - 1);      // right-edge window valid?

    const size_t base = ((size_t)n * Cc * Hh + h) * VW + v;   // channel 0

    float acc[NS * 4];
    #pragma unroll
    for (int i = 0; i < NS * 4; i++) acc[i] = 0.0f;

    const float4 z4 = make_float4(0.f, 0.f, 0.f, 0.f);

    const float4* p1 = f1 + base;
    const float4* p2 = f2 + base;

    #pragma unroll 4
    for (int c = 0; c < Cc; c++) {
        const float4 a  = __ldcs(p1);          // read-once stream: evict-first
        const float4 c0 = __ldg(p2);
        const float4 cm = pm ? __ldg(p2 - 1) : z4;   // f2[w-4..w-1]
        const float4 cp = pp ? __ldg(p2 + 1) : z4;   // f2[w+4..w+7]
        p1 += CH4;
        p2 += CH4;

        // window win[k] = f2pad[w-4+k], k=0..11
        float win[12];
        win[0] = cm.x; win[1] = cm.y; win[2]  = cm.z; win[3]  = cm.w;
        win[4] = c0.x; win[5] = c0.y; win[6]  = c0.z; win[7]  = c0.w;
        win[8] = cp.x; win[9] = cp.y; win[10] = cp.z; win[11] = cp.w;

        float av[4];
        av[0] = a.x; av[1] = a.y; av[2] = a.z; av[3] = a.w;

        #pragma unroll
        for (int d = 0; d < NS; d++) {
            #pragma unroll
            for (int j = 0; j < 4; j++) {
                acc[d * 4 + j] = fmaf(av[j], win[j + d], acc[d * 4 + j]);
            }
        }
    }

    // Epilogue: channel mean, streaming float4 stores. out[n][d][h][w..w+3]
    const float inv = 1.0f / (float)Cc;
    float4* o4 = (float4*)out;
    #pragma unroll
    for (int d = 0; d < NS; d++) {
        float4 o;
        o.x = acc[d * 4 + 0] * inv;
        o.y = acc[d * 4 + 1] * inv;
        o.z = acc[d * 4 + 2] * inv;
        o.w = acc[d * 4 + 3] * inv;
        __stcs(&o4[((size_t)(n * NS + d) * Hh + h) * VW + v], o);
    }
}

extern "C" void kernel_launch(void* const* d_in, const int* in_sizes, int n_in,
                              void* d_out, int out_size)
{
    const float4* f1 = (const float4*)d_in[0];
    const float4* f2 = (const float4*)d_in[1];
    float* out = (float*)d_out;
    (void)in_sizes; (void)n_in; (void)out_size;

    const int total = Nn * Hh * VW;          // 122880 threads, 1 float4 each
    dim3 grid(total / TPB);                  // 1920 blocks of 64
    dim3 block(TPB);
    costvol1d_kernel<<<grid, block>>>(f1, f2, out);
}

// round 6
// speedup vs baseline: 1.1187x; 1.0148x over previous
#include <cuda_runtime.h>

// CostVolume1D: out[n,d,h,w] = (1/C) * sum_c f1[n,c,h,w] * f2pad[n,c,h,w+d-4]
// f1,f2: [4,128,192,640] fp32. Barrier-free, smem-free, float4 per thread.
// R6: R3 structure (TPB=128, grid 960, no cache hints) + unroll 8 and
//     launch_bounds(128,6) (reg cap 85) for a deeper rolling LDG window.

#define Nn   4
#define Cc   128
#define Hh   192
#define Ww   640
#define Dd   4
#define NS   (2*Dd + 1)       // 9
#define TPB  128
#define VW   (Ww / 4)         // 160 float4 per row
#define CH4  ((size_t)Hh * VW) // channel stride in float4 units (30720)

__global__ __launch_bounds__(TPB, 6)
void costvol1d_kernel(const float4* __restrict__ f1,
                      const float4* __restrict__ f2,
                      float* __restrict__ out)
{
    const int gid = blockIdx.x * TPB + threadIdx.x;   // 0 .. N*H*VW-1 = 122879
    const int v   = gid % VW;          // float4 index within row
    const int row = gid / VW;          // n*Hh + h
    const int n   = row / Hh;
    const int h   = row % Hh;

    const bool pm = (v > 0);           // left-edge window valid?
    const bool pp = (v < VW - 1);      // right-edge window valid?

    const size_t base = ((size_t)n * Cc * Hh + h) * VW + v;   // channel 0

    float acc[NS * 4];
    #pragma unroll
    for (int i = 0; i < NS * 4; i++) acc[i] = 0.0f;

    const float4 z4 = make_float4(0.f, 0.f, 0.f, 0.f);

    #pragma unroll 8
    for (int c = 0; c < Cc; c++) {
        const size_t o = base + (size_t)c * CH4;

        const float4 a  = f1[o];
        const float4 c0 = f2[o];
        const float4 cm = pm ? f2[o - 1] : z4;   // f2[w-4..w-1]
        const float4 cp = pp ? f2[o + 1] : z4;   // f2[w+4..w+7]

        // window win[k] = f2pad[w-4+k], k=0..11
        float win[12];
        win[0] = cm.x; win[1] = cm.y; win[2]  = cm.z; win[3]  = cm.w;
        win[4] = c0.x; win[5] = c0.y; win[6]  = c0.z; win[7]  = c0.w;
        win[8] = cp.x; win[9] = cp.y; win[10] = cp.z; win[11] = cp.w;

        float av[4];
        av[0] = a.x; av[1] = a.y; av[2] = a.z; av[3] = a.w;

        #pragma unroll
        for (int d = 0; d < NS; d++) {
            #pragma unroll
            for (int j = 0; j < 4; j++) {
                acc[d * 4 + j] = fmaf(av[j], win[j + d], acc[d * 4 + j]);
            }
        }
    }

    // Epilogue: channel mean, float4 stores. out[n][d][h][w..w+3]
    const float inv = 1.0f / (float)Cc;
    float4* o4 = (float4*)out;
    #pragma unroll
    for (int d = 0; d < NS; d++) {
        float4 o;
        o.x = acc[d * 4 + 0] * inv;
        o.y = acc[d * 4 + 1] * inv;
        o.z = acc[d * 4 + 2] * inv;
        o.w = acc[d * 4 + 3] * inv;
        o4[((size_t)(n * NS + d) * Hh + h) * VW + v] = o;
    }
}

extern "C" void kernel_launch(void* const* d_in, const int* in_sizes, int n_in,
                              void* d_out, int out_size)
{
    const float4* f1 = (const float4*)d_in[0];
    const float4* f2 = (const float4*)d_in[1];
    float* out = (float*)d_out;
    (void)in_sizes; (void)n_in; (void)out_size;

    const int total = Nn * Hh * VW;          // 122880 threads, 1 float4 each
    dim3 grid(total / TPB);                  // 960 blocks
    dim3 block(TPB);
    costvol1d_kernel<<<grid, block>>>(f1, f2, out);
}

// round 7
// speedup vs baseline: 1.8601x; 1.6628x over previous
#include <cuda_runtime.h>

// CostVolume1D: out[n,d,h,w] = (1/C) * sum_c f1[n,c,h,w] * f2pad[n,c,h,w+d-4]
// f1,f2: [4,128,192,640] fp32. R3 structure (TPB=128, grid 960, unroll 4)
// with the f2 halo obtained via warp shuffles instead of extra LDG.128s:
// a warp covers 32 consecutive float4's of one row (160 = 5*32), so lane l's
// left/right neighbor float4 is lane l-1 / l+1's center load. Only lanes 0/31
// issue one predicated edge load. Loads/channel: 4 -> ~2.06.

#define Nn   4
#define Cc   128
#define Hh   192
#define Ww   640
#define Dd   4
#define NS   (2*Dd + 1)       // 9
#define TPB  128
#define VW   (Ww / 4)         // 160 float4 per row
#define CH4  ((size_t)Hh * VW) // channel stride in float4 units (30720)

__global__ __launch_bounds__(TPB, 7)
void costvol1d_kernel(const float4* __restrict__ f1,
                      const float4* __restrict__ f2,
                      float* __restrict__ out)
{
    const int gid  = blockIdx.x * TPB + threadIdx.x;  // 0 .. N*H*VW-1
    const int v    = gid % VW;         // float4 index within row
    const int row  = gid / VW;         // n*Hh + h
    const int n    = row / Hh;
    const int h    = row % Hh;
    const int lane = threadIdx.x & 31;

    // Edge-lane predicated load: lane 0 fetches f2[o-1] (if v>0),
    // lane 31 fetches f2[o+1] (if v<VW-1). Other lanes never load it.
    const bool  evalid = (lane == 0) ? (v > 0)
                       : (lane == 31) ? (v < VW - 1) : false;
    const long  eoff   = (lane == 0) ? -1L : 1L;

    const size_t base = ((size_t)n * Cc * Hh + h) * VW + v;   // channel 0

    float acc[NS * 4];
    #pragma unroll
    for (int i = 0; i < NS * 4; i++) acc[i] = 0.0f;

    const float4 z4 = make_float4(0.f, 0.f, 0.f, 0.f);

    #pragma unroll 4
    for (int c = 0; c < Cc; c++) {
        const size_t o = base + (size_t)c * CH4;

        const float4 a  = f1[o];
        const float4 c0 = f2[o];
        const float4 e  = evalid ? f2[o + eoff] : z4;

        // Neighbor float4s via warp shuffle of c0.
        float4 cm, cp;
        cm.x = __shfl_up_sync(0xffffffffu, c0.x, 1);
        cm.y = __shfl_up_sync(0xffffffffu, c0.y, 1);
        cm.z = __shfl_up_sync(0xffffffffu, c0.z, 1);
        cm.w = __shfl_up_sync(0xffffffffu, c0.w, 1);
        cp.x = __shfl_down_sync(0xffffffffu, c0.x, 1);
        cp.y = __shfl_down_sync(0xffffffffu, c0.y, 1);
        cp.z = __shfl_down_sync(0xffffffffu, c0.z, 1);
        cp.w = __shfl_down_sync(0xffffffffu, c0.w, 1);
        if (lane == 0)  cm = e;   // left edge of warp's 32-v span
        if (lane == 31) cp = e;   // right edge

        // window win[k] = f2pad[w-4+k], k=0..11
        float win[12];
        win[0] = cm.x; win[1] = cm.y; win[2]  = cm.z; win[3]  = cm.w;
        win[4] = c0.x; win[5] = c0.y; win[6]  = c0.z; win[7]  = c0.w;
        win[8] = cp.x; win[9] = cp.y; win[10] = cp.z; win[11] = cp.w;

        float av[4];
        av[0] = a.x; av[1] = a.y; av[2] = a.z; av[3] = a.w;

        #pragma unroll
        for (int d = 0; d < NS; d++) {
            #pragma unroll
            for (int j = 0; j < 4; j++) {
                acc[d * 4 + j] = fmaf(av[j], win[j + d], acc[d * 4 + j]);
            }
        }
    }

    // Epilogue: channel mean, float4 stores. out[n][d][h][w..w+3]
    const float inv = 1.0f / (float)Cc;
    float4* o4 = (float4*)out;
    #pragma unroll
    for (int d = 0; d < NS; d++) {
        float4 o;
        o.x = acc[d * 4 + 0] * inv;
        o.y = acc[d * 4 + 1] * inv;
        o.z = acc[d * 4 + 2] * inv;
        o.w = acc[d * 4 + 3] * inv;
        o4[((size_t)(n * NS + d) * Hh + h) * VW + v] = o;
    }
}

extern "C" void kernel_launch(void* const* d_in, const int* in_sizes, int n_in,
                              void* d_out, int out_size)
{
    const float4* f1 = (const float4*)d_in[0];
    const float4* f2 = (const float4*)d_in[1];
    float* out = (float*)d_out;
    (void)in_sizes; (void)n_in; (void)out_size;

    const int total = Nn * Hh * VW;          // 122880 threads, 1 float4 each
    dim3 grid(total / TPB);                  // 960 blocks (single full wave)
    dim3 block(TPB);
    costvol1d_kernel<<<grid, block>>>(f1, f2, out);
}